// round 6
// baseline (speedup 1.0000x reference)
#include <cuda_runtime.h>
#include <cuda_bf16.h>
#include <math.h>
#include <stdint.h>

// FlashChatglmAttention: B=4 S=1024 HID=4096 NH=32 HS=128 ROT=64
// R6: fused-split bf16 mma.sync GEMM with 512-thread CTA (16 warps, 128x256
// tile, 4x4 warp grid) to raise warps/SMSP from 2 to 4. 3-stage cp.async ring.

#define TT    4096
#define HIDN  4096
#define NHEAD 32
#define HSZ   128
#define SEQ   1024
#define BATCH 4
#define GK    4096
#define LDP   8192      // packed row stride (hi|lo)

// ---------------- scratch (allocation-free) ----------------
__device__ float g_qkv [(size_t)TT * 3 * HIDN];
__device__ float g_q   [(size_t)TT * HIDN];
__device__ float g_attn[(size_t)TT * HIDN];
__device__ __nv_bfloat16 g_pa [(size_t)TT * LDP];
__device__ __nv_bfloat16 g_pbq[(size_t)3 * HIDN * LDP];
__device__ __nv_bfloat16 g_pbd[(size_t)HIDN * LDP];

// ---------------- PTX helpers (baseline ISA only) ----------------
__device__ __forceinline__ uint32_t smem_u32(const void* p) {
    uint32_t a;
    asm("{ .reg .u64 t; cvta.to.shared.u64 t, %1; cvt.u32.u64 %0, t; }" : "=r"(a) : "l"(p));
    return a;
}
__device__ __forceinline__ void cp_async16(uint32_t saddr, const void* gaddr) {
    asm volatile("cp.async.cg.shared.global [%0], [%1], 16;" :: "r"(saddr), "l"(gaddr));
}
__device__ __forceinline__ void cp_commit() { asm volatile("cp.async.commit_group;"); }
template<int N> __device__ __forceinline__ void cp_wait() {
    asm volatile("cp.async.wait_group %0;" :: "n"(N));
}
__device__ __forceinline__ void ldsm4(uint32_t* r, uint32_t addr) {
    asm volatile("ldmatrix.sync.aligned.m8n8.x4.shared.b16 {%0,%1,%2,%3}, [%4];"
                 : "=r"(r[0]), "=r"(r[1]), "=r"(r[2]), "=r"(r[3]) : "r"(addr));
}
__device__ __forceinline__ void mma16816(float* c, const uint32_t* a, const uint32_t* b) {
    asm volatile("mma.sync.aligned.m16n8k16.row.col.f32.bf16.bf16.f32 "
                 "{%0,%1,%2,%3}, {%4,%5,%6,%7}, {%8,%9}, {%0,%1,%2,%3};"
                 : "+f"(c[0]), "+f"(c[1]), "+f"(c[2]), "+f"(c[3])
                 : "r"(a[0]), "r"(a[1]), "r"(a[2]), "r"(a[3]), "r"(b[0]), "r"(b[1]));
}

// ---------------------------------------------------------------------------
// Pack kernels: fp32 -> bf16 hi | lo (residual).
// ---------------------------------------------------------------------------
__global__ __launch_bounds__(256) void pack_a(const float* __restrict__ X,
                                              __nv_bfloat16* __restrict__ Y) {
    const int idx = blockIdx.x * 256 + threadIdx.x;
    const int m = idx >> 12, k = idx & 4095;
    const float x = X[idx];
    const __nv_bfloat16 h = __float2bfloat16(x);
    const float r = x - __bfloat162float(h);
    Y[(size_t)m * LDP + k]      = h;
    Y[(size_t)m * LDP + GK + k] = __float2bfloat16(r);
}

// transpose pack: W[K][N] -> Y[N][hi(K)|lo(K)]
__global__ __launch_bounds__(1024) void pack_bt(const float* __restrict__ W,
                                                __nv_bfloat16* __restrict__ Y, int N) {
    __shared__ float sm[32][33];
    const int n0 = blockIdx.x << 5, k0 = blockIdx.y << 5;
    sm[threadIdx.y][threadIdx.x] = W[(size_t)(k0 + threadIdx.y) * N + n0 + threadIdx.x];
    __syncthreads();
    const float x = sm[threadIdx.x][threadIdx.y];       // W[k0+tx][n0+ty]
    const int n = n0 + threadIdx.y, k = k0 + threadIdx.x;
    const __nv_bfloat16 h = __float2bfloat16(x);
    const float r = x - __bfloat162float(h);
    Y[(size_t)n * LDP + k]      = h;
    Y[(size_t)n * LDP + GK + k] = __float2bfloat16(r);
}

// ---------------------------------------------------------------------------
// Fused-split bf16 mma.sync GEMM. 128x256 CTA tile, BK=32, 512 threads,
// 16 warps (4x4), 32x64 warp tile. Per k-tile smem: Ah|Al|Bh|Bl.
// 3-stage cp.async ring, one __syncthreads per k-tile.
// ---------------------------------------------------------------------------
#define ATILEB 10240u                  // A operand tile (128 rows * 80B)
#define BTILEB 20480u                  // B operand tile (256 rows * 80B)
#define STAGEB (2u * ATILEB + 2u * BTILEB)   // 61440
#define NSTAGE 3
#define GEMM_SMEM (NSTAGE * STAGEB)    // 184320 B

__global__ __launch_bounds__(512, 1) void tgemm(
    const __nv_bfloat16* __restrict__ A, const __nv_bfloat16* __restrict__ Bt,
    const float* __restrict__ bias, float* __restrict__ C, int M, int N)
{
    extern __shared__ __align__(16) char smraw[];
    const uint32_t sS = smem_u32(smraw);

    const int tid = threadIdx.x;
    const int wid = tid >> 5, lane = tid & 31;
    const int warp_m = wid >> 2, warp_n = wid & 3;

    const int m0 = blockIdx.y << 7, n0 = blockIdx.x << 8;
    const __nv_bfloat16* Ap = A + (size_t)m0 * LDP;
    const __nv_bfloat16* Bp = Bt + (size_t)n0 * LDP;

    // ldmatrix per-lane address components
    const int arow = lane & 15;                       // A: row within m16 tile
    const int akb  = (lane >> 4) * 16;                // A: k-byte offset
    const int brow = ((lane >> 4) << 3) + (lane & 7); // B: row within n16 tile
    const int bkb  = ((lane >> 3) & 1) * 16;          // B: k-byte offset

    float c[2][8][4];
    #pragma unroll
    for (int i = 0; i < 2; i++)
        #pragma unroll
        for (int j = 0; j < 8; j++)
            #pragma unroll
            for (int v = 0; v < 4; v++) c[i][j][v] = 0.f;

    const int NT = GK / 32;   // 128 k-tiles

    // loader: A 1024 chunks (hi|lo), B 2048 chunks (hi|lo); 6 chunks/thread
    auto issue = [&](int t) {
        const uint32_t sb = sS + (uint32_t)(t % NSTAGE) * STAGEB;
        const int ko = t * 32;
        #pragma unroll
        for (int j = 0; j < 2; j++) {               // A chunks
            const int id = tid + (j << 9);          // 0..1023
            const int tile = id >> 9, w = id & 511;
            const int row = w >> 2, ch = w & 3;
            cp_async16(sb + tile * ATILEB + row * 80 + ch * 16,
                       Ap + (size_t)row * LDP + (tile ? GK : 0) + ko + ch * 8);
        }
        #pragma unroll
        for (int j = 0; j < 4; j++) {               // B chunks
            const int id = tid + (j << 9);          // 0..2047
            const int tile = id >> 10, w = id & 1023;
            const int row = w >> 2, ch = w & 3;
            cp_async16(sb + 2 * ATILEB + tile * BTILEB + row * 80 + ch * 16,
                       Bp + (size_t)row * LDP + (tile ? GK : 0) + ko + ch * 8);
        }
        cp_commit();
    };

    issue(0); issue(1);
    for (int t = 0; t < NT; t++) {
        cp_wait<1>();
        __syncthreads();
        if (t + 2 < NT) issue(t + 2);
        const uint32_t bufo = sS + (uint32_t)(t % NSTAGE) * STAGEB;
        #pragma unroll
        for (int ks = 0; ks < 2; ks++) {
            uint32_t ah[2][4], al[2][4];
            #pragma unroll
            for (int i = 0; i < 2; i++) {
                const uint32_t ra = bufo + (warp_m * 32 + i * 16 + arow) * 80 + ks * 32 + akb;
                ldsm4(ah[i], ra);
                ldsm4(al[i], ra + ATILEB);
            }
            #pragma unroll
            for (int g = 0; g < 4; g++) {
                uint32_t bh[4], bl[4];
                const uint32_t rb = bufo + 2 * ATILEB
                                  + (warp_n * 64 + g * 16 + brow) * 80 + ks * 32 + bkb;
                ldsm4(bh, rb);
                ldsm4(bl, rb + BTILEB);
                #pragma unroll
                for (int i = 0; i < 2; i++) {
                    mma16816(c[i][g * 2 + 0], ah[i], &bh[0]);
                    mma16816(c[i][g * 2 + 1], ah[i], &bh[2]);
                    mma16816(c[i][g * 2 + 0], al[i], &bh[0]);
                    mma16816(c[i][g * 2 + 1], al[i], &bh[2]);
                    mma16816(c[i][g * 2 + 0], ah[i], &bl[0]);
                    mma16816(c[i][g * 2 + 1], ah[i], &bl[2]);
                }
            }
        }
    }

    // epilogue
    const int gid = lane >> 2, tg = lane & 3;
    #pragma unroll
    for (int i = 0; i < 2; i++) {
        const int row = m0 + warp_m * 32 + i * 16 + gid;
        #pragma unroll
        for (int j = 0; j < 8; j++) {
            const int col = n0 + warp_n * 64 + j * 8 + tg * 2;
            float b0 = 0.f, b1 = 0.f;
            if (bias) { b0 = bias[col]; b1 = bias[col + 1]; }
            *(float2*)&C[(size_t)row * N + col] =
                make_float2(c[i][j][0] + b0, c[i][j][1] + b1);
            *(float2*)&C[(size_t)(row + 8) * N + col] =
                make_float2(c[i][j][2] + b0, c[i][j][3] + b1);
        }
    }
}

// ---------------------------------------------------------------------------
// Rotary (first 64 dims/head) + kv scatter. qkv: [t][12288] = q|k|v (NH,HS).
// ---------------------------------------------------------------------------
__global__ __launch_bounds__(256) void rotary_scatter(
    const float* __restrict__ qkv, const float* __restrict__ cosb,
    const float* __restrict__ sinb, const int* __restrict__ slots,
    float* __restrict__ qout, float* __restrict__ kout, float* __restrict__ vout)
{
    const int idx = blockIdx.x * 256 + threadIdx.x;
    const int t = idx >> 12;
    const int hd = idx & 4095;
    const int d = hd & 127;
    const float* base = qkv + (size_t)t * 12288;
    float qv = base[hd];
    float kv = base[4096 + hd];
    const float vv = base[8192 + hd];
    if (d < 64) {
        const int half = d & 31;
        const float c = cosb[(t << 5) + half];
        const float s = sinb[(t << 5) + half];
        if (d < 32) {
            qv = qv * c - base[hd + 32] * s;
            kv = kv * c - base[4096 + hd + 32] * s;
        } else {
            qv = qv * c + base[hd - 32] * s;
            kv = kv * c + base[4096 + hd - 32] * s;
        }
    }
    qout[idx] = qv;
    const size_t ko = ((size_t)slots[t] << 12) + hd;
    kout[ko] = kv;
    vout[ko] = vv;
}

// ---------------------------------------------------------------------------
// Causal flash attention, fp32. Br=Bc=64, 256 threads. grid (S/64, NH, B).
// ---------------------------------------------------------------------------
__global__ __launch_bounds__(256) void attn_kernel(
    const float* __restrict__ Q, const float* __restrict__ Kc,
    const float* __restrict__ Vc, float* __restrict__ O)
{
    extern __shared__ float smf[];
    float* Qs   = smf;
    float* Ks   = Qs + 64 * 128;
    float* Vs   = Ks + 64 * 129;
    float* Ps   = Vs + 64 * 132;
    float* mrow = Ps + 64 * 66;
    float* lrow = mrow + 64;
    float* arow = lrow + 64;

    const int qi = blockIdx.x, h = blockIdx.y, b = blockIdx.z;
    const int tid = threadIdx.x;
    const int tx = tid & 15, ty = tid >> 4;
    const int q0 = qi << 6;
    const float scale = 0.08838834764831845f;

    #pragma unroll
    for (int i = 0; i < 8; i++) {
        const int f = tid + (i << 8);
        const int r = f >> 5, dq = f & 31;
        const float4 v = *(const float4*)&Q[(size_t)(b * SEQ + q0 + r) * HIDN + h * HSZ + dq * 4];
        *(float4*)&Qs[r * 128 + dq * 4] =
            make_float4(v.x * scale, v.y * scale, v.z * scale, v.w * scale);
    }
    if (tid < 64) { mrow[tid] = -1e30f; lrow[tid] = 0.f; }
    float o[4][8];
    #pragma unroll
    for (int i = 0; i < 4; i++)
        #pragma unroll
        for (int j = 0; j < 8; j++) o[i][j] = 0.f;
    __syncthreads();

    for (int kt = 0; kt <= qi; kt++) {
        #pragma unroll
        for (int i = 0; i < 8; i++) {
            const int f = tid + (i << 8);
            const int r = f >> 5, dq = f & 31;
            const size_t g = (size_t)(b * SEQ + (kt << 6) + r) * HIDN + h * HSZ + dq * 4;
            const float4 kv = *(const float4*)&Kc[g];
            Ks[r * 129 + dq * 4 + 0] = kv.x; Ks[r * 129 + dq * 4 + 1] = kv.y;
            Ks[r * 129 + dq * 4 + 2] = kv.z; Ks[r * 129 + dq * 4 + 3] = kv.w;
            *(float4*)&Vs[r * 132 + dq * 4] = *(const float4*)&Vc[g];
        }
        __syncthreads();

        float s[4][4];
        #pragma unroll
        for (int i = 0; i < 4; i++)
            #pragma unroll
            for (int j = 0; j < 4; j++) s[i][j] = 0.f;
        #pragma unroll 4
        for (int d = 0; d < 128; d++) {
            float qr[4], kr[4];
            #pragma unroll
            for (int i = 0; i < 4; i++) qr[i] = Qs[(ty * 4 + i) * 128 + d];
            #pragma unroll
            for (int j = 0; j < 4; j++) kr[j] = Ks[(tx * 4 + j) * 129 + d];
            #pragma unroll
            for (int i = 0; i < 4; i++)
                #pragma unroll
                for (int j = 0; j < 4; j++)
                    s[i][j] = fmaf(qr[i], kr[j], s[i][j]);
        }
        #pragma unroll
        for (int i = 0; i < 4; i++) {
            const int qr_ = q0 + ty * 4 + i;
            #pragma unroll
            for (int j = 0; j < 4; j++) {
                const int kc = (kt << 6) + tx * 4 + j;
                Ps[(ty * 4 + i) * 66 + tx * 4 + j] = (kc <= qr_) ? s[i][j] : -1e30f;
            }
        }
        __syncthreads();

        if (tid < 64) {
            float mold = mrow[tid];
            float mnew = mold;
            float* pr = &Ps[tid * 66];
            #pragma unroll 8
            for (int cc = 0; cc < 64; cc++) mnew = fmaxf(mnew, pr[cc]);
            const float alpha = __expf(mold - mnew);
            float lsum = 0.f;
            #pragma unroll 8
            for (int cc = 0; cc < 64; cc++) {
                const float p = __expf(pr[cc] - mnew);
                pr[cc] = p; lsum += p;
            }
            lrow[tid] = lrow[tid] * alpha + lsum;
            mrow[tid] = mnew;
            arow[tid] = alpha;
        }
        __syncthreads();

        float al[4];
        #pragma unroll
        for (int i = 0; i < 4; i++) al[i] = arow[ty * 4 + i];
        #pragma unroll
        for (int i = 0; i < 4; i++)
            #pragma unroll
            for (int j = 0; j < 8; j++) o[i][j] *= al[i];
        #pragma unroll 2
        for (int k = 0; k < 64; k++) {
            float p[4];
            #pragma unroll
            for (int i = 0; i < 4; i++) p[i] = Ps[(ty * 4 + i) * 66 + k];
            const float4 v0 = *(const float4*)&Vs[k * 132 + tx * 8];
            const float4 v1 = *(const float4*)&Vs[k * 132 + tx * 8 + 4];
            const float vv[8] = {v0.x, v0.y, v0.z, v0.w, v1.x, v1.y, v1.z, v1.w};
            #pragma unroll
            for (int i = 0; i < 4; i++)
                #pragma unroll
                for (int j = 0; j < 8; j++)
                    o[i][j] = fmaf(p[i], vv[j], o[i][j]);
        }
        __syncthreads();
    }

    #pragma unroll
    for (int i = 0; i < 4; i++) {
        const float inv = 1.f / lrow[ty * 4 + i];
        float* dst = &O[(size_t)(b * SEQ + q0 + ty * 4 + i) * HIDN + h * HSZ + tx * 8];
        *(float4*)dst       = make_float4(o[i][0] * inv, o[i][1] * inv, o[i][2] * inv, o[i][3] * inv);
        *(float4*)(dst + 4) = make_float4(o[i][4] * inv, o[i][5] * inv, o[i][6] * inv, o[i][7] * inv);
    }
}

// ---------------------------------------------------------------------------
extern "C" void kernel_launch(void* const* d_in, const int* in_sizes, int n_in,
                              void* d_out, int out_size)
{
    (void)in_sizes; (void)n_in; (void)out_size;
    const float* hs     = (const float*)d_in[0];
    const float* cosb   = (const float*)d_in[1];
    const float* sinb   = (const float*)d_in[2];
    const float* wqkv   = (const float*)d_in[3];
    const float* bqkv   = (const float*)d_in[4];
    const float* wdense = (const float*)d_in[5];
    const int*   slots  = (const int*)d_in[8];

    float* out = (float*)d_out;
    float* kvk = out + (size_t)TT * HIDN;
    float* kvv = kvk + (size_t)TT * HIDN;

    float *qkv_p, *q_p, *attn_p;
    __nv_bfloat16 *pa, *pbq, *pbd;
    cudaGetSymbolAddress((void**)&qkv_p,  g_qkv);
    cudaGetSymbolAddress((void**)&q_p,    g_q);
    cudaGetSymbolAddress((void**)&attn_p, g_attn);
    cudaGetSymbolAddress((void**)&pa,     g_pa);
    cudaGetSymbolAddress((void**)&pbq,    g_pbq);
    cudaGetSymbolAddress((void**)&pbd,    g_pbd);

    cudaFuncSetAttribute(tgemm, cudaFuncAttributeMaxDynamicSharedMemorySize, GEMM_SMEM);

    // pack operands (hi/lo bf16 split)
    pack_a<<<(TT * GK) / 256, 256>>>(hs, pa);
    pack_bt<<<dim3(3 * HIDN / 32, GK / 32), dim3(32, 32)>>>(wqkv, pbq, 3 * HIDN);
    pack_bt<<<dim3(HIDN / 32, GK / 32), dim3(32, 32)>>>(wdense, pbd, HIDN);

    // 1. QKV projection on tensor cores (+bias)
    tgemm<<<dim3(3 * HIDN / 256, TT / 128), 512, GEMM_SMEM>>>(pa, pbq, bqkv, qkv_p, TT, 3 * HIDN);

    // 2. rotary + kv-cache scatter
    rotary_scatter<<<(TT * HIDN) / 256, 256>>>(qkv_p, cosb, sinb, slots, q_p, kvk, kvv);

    // 3. causal flash attention (fp32 SIMT)
    const size_t asmem = (size_t)(64 * 128 + 64 * 129 + 64 * 132 + 64 * 66 + 192) * sizeof(float);
    cudaFuncSetAttribute(attn_kernel, cudaFuncAttributeMaxDynamicSharedMemorySize, (int)asmem);
    attn_kernel<<<dim3(SEQ / 64, NHEAD, BATCH), 256, asmem>>>(q_p, kvk, kvv, attn_p);

    // 4. dense projection on tensor cores
    pack_a<<<(TT * GK) / 256, 256>>>(attn_p, pa);
    tgemm<<<dim3(HIDN / 256, TT / 128), 512, GEMM_SMEM>>>(pa, pbd, nullptr, out, TT, HIDN);
}